// round 15
// baseline (speedup 1.0000x reference)
#include <cuda_runtime.h>
#include <cuda_bf16.h>
#include <cstdint>

#define NN 50000
#define EMAX 1000000
#define SCAN_NB ((NN + 511) / 512)   // 98 chunks of 512

// ---------------- scratch: hi/lo bf16 number system (no allocations) ----------------
static __device__ __align__(16) ushort g_A1h[NN * 128];  // [agg(x) | x] hi
static __device__ __align__(16) ushort g_A1l[NN * 128];  // lo
static __device__ __align__(16) ushort g_A2h[NN * 256];  // [agg(h) | h] hi
static __device__ __align__(16) ushort g_A2l[NN * 256];  // lo
static __device__ __align__(16) ushort g_W1h[128 * 128]; // [Wl1;Wr1]^T hi
static __device__ __align__(16) ushort g_W1l[128 * 128];
static __device__ __align__(16) ushort g_W2h[384 * 256]; // [Wl2;Wr2]^T hi, n-padded
static __device__ __align__(16) ushort g_W2l[384 * 256];
static __device__ int g_idx64;
static __device__ int g_degi[NN];
static __device__ int g_rowptr[NN + 1];
static __device__ int g_cursor[NN];
static __device__ int g_colsrc[EMAX];
static __device__ int g_part[128];
static __device__ int g_partoff[128];

__device__ __forceinline__ void bsplit(float v, ushort& h, ushort& l) {
    __nv_bfloat16 hb = __float2bfloat16(v);
    h = __bfloat16_as_ushort(hb);
    l = __bfloat16_as_ushort(__float2bfloat16(v - __bfloat162float(hb)));
}
__device__ __forceinline__ float bjoin(ushort h, ushort l) {
    return __bfloat162float(__ushort_as_bfloat16(h)) +
           __bfloat162float(__ushort_as_bfloat16(l));
}

// ---------------- threefry2x32 dropout, JAX partitionable (o0 ^ o1) ----------------
__device__ __forceinline__ float tf_drop(float v, unsigned idx) {
    unsigned x0 = 0u, x1 = idx;
    const unsigned k0 = 0u, k1 = 42u;
    const unsigned k2c = 0u ^ 42u ^ 0x1BD11BDAu;
    x0 += k0; x1 += k1;
#define TF_R(r) { x0 += x1; x1 = __funnelshift_l(x1, x1, (r)); x1 ^= x0; }
    TF_R(13) TF_R(15) TF_R(26) TF_R(6)
    x0 += k1;  x1 += k2c + 1u;
    TF_R(17) TF_R(29) TF_R(16) TF_R(24)
    x0 += k2c; x1 += k0 + 2u;
    TF_R(13) TF_R(15) TF_R(26) TF_R(6)
    x0 += k0;  x1 += k1 + 3u;
    TF_R(17) TF_R(29) TF_R(16) TF_R(24)
    x0 += k1;  x1 += k2c + 4u;
    TF_R(13) TF_R(15) TF_R(26) TF_R(6)
    x0 += k2c; x1 += k0 + 5u;
#undef TF_R
    unsigned bits = x0 ^ x1;
    float u = __uint_as_float((bits >> 9) | 0x3f800000u) - 1.0f;
    return (u < 0.5f) ? v * 2.0f : 0.0f;
}

// ---------------- mma.sync m16n8k16 bf16 + ldmatrix ----------------
__device__ __forceinline__ void mma16816(float* c, const unsigned* a, const unsigned* b) {
    asm volatile(
        "mma.sync.aligned.m16n8k16.row.col.f32.bf16.bf16.f32 "
        "{%0,%1,%2,%3}, {%4,%5,%6,%7}, {%8,%9}, {%0,%1,%2,%3};"
        : "+f"(c[0]), "+f"(c[1]), "+f"(c[2]), "+f"(c[3])
        : "r"(a[0]), "r"(a[1]), "r"(a[2]), "r"(a[3]), "r"(b[0]), "r"(b[1]));
}

__device__ __forceinline__ void ldsm4(unsigned* r, uint32_t addr) {
    asm volatile("ldmatrix.sync.aligned.m8n8.x4.shared.b16 {%0,%1,%2,%3}, [%4];"
                 : "=r"(r[0]), "=r"(r[1]), "=r"(r[2]), "=r"(r[3]) : "r"(addr));
}

__device__ __forceinline__ uint32_t smem_u32(const void* p) {
    uint32_t a;
    asm("{ .reg .u64 t; cvta.to.shared.u64 t, %1; cvt.u32.u64 %0, t; }" : "=r"(a) : "l"(p));
    return a;
}

#define SSTR 40   // smem row stride (ushorts): 32 data + 8 pad; rows 80B (16B-aligned)

// copy 128x32 ushort tile from global (row-major, given stride) into smem
__device__ __forceinline__ void copy_tile(const ushort* __restrict__ src, int stride,
                                          int r0, int rowlim, int kb,
                                          ushort* dst, int tid) {
    for (int i = tid; i < 512; i += 256) {
        int r = i >> 2, c8 = (i & 3) * 8;
        int gr = r0 + r;
        uint4 v = make_uint4(0u, 0u, 0u, 0u);
        if (gr < rowlim)
            v = *(const uint4*)(src + (long long)gr * stride + kb + c8);
        *(uint4*)(dst + r * SSTR + c8) = v;
    }
}

// ---------------- dtype detection ----------------
__global__ void k_detect(const void* __restrict__ ei) {
    const long long* p = (const long long*)ei;
    long long v = p[threadIdx.x];
    unsigned bad = __ballot_sync(0xffffffffu, (unsigned long long)v >= (unsigned long long)NN);
    __shared__ int s_bad;
    if (threadIdx.x == 0) s_bad = 0;
    __syncthreads();
    if ((threadIdx.x & 31) == 0 && bad) atomicOr(&s_bad, 1);
    __syncthreads();
    if (threadIdx.x == 0) g_idx64 = s_bad ? 0 : 1;
}

__device__ __forceinline__ void load_edge(const void* ei, int E, int e, int& src, int& dst) {
    if (g_idx64) {
        const long long* p = (const long long*)ei;
        src = (int)p[e];
        dst = (int)p[E + e];
    } else {
        const int* p = (const int*)ei;
        src = p[e];
        dst = p[E + e];
    }
}

// ---------------- init: split x + weights into hi/lo, zero deg ----------------
__global__ void k_init(const float* __restrict__ x,
                       const float* __restrict__ Wl1, const float* __restrict__ Wr1,
                       const float* __restrict__ Wl2, const float* __restrict__ Wr2) {
    const int T0 = NN * 64;
    const int T1 = T0 + NN;
    const int T2 = T1 + 128 * 128;
    const int T3 = T2 + 384 * 256;
    for (int i = blockIdx.x * blockDim.x + threadIdx.x; i < T3;
         i += gridDim.x * blockDim.x) {
        if (i < T0) {
            int row = i >> 6, col = i & 63;
            ushort h, l;
            bsplit(x[i], h, l);
            g_A1h[row * 128 + 64 + col] = h;
            g_A1l[row * 128 + 64 + col] = l;
        } else if (i < T1) {
            g_degi[i - T0] = 0;
        } else if (i < T2) {
            int j = i - T1;
            int n = j >> 7, k = j & 127;
            float v = (k < 64) ? Wl1[k * 128 + n] : Wr1[(k - 64) * 128 + n];
            ushort h, l;
            bsplit(v, h, l);
            g_W1h[j] = h;
            g_W1l[j] = l;
        } else {
            int j = i - T2;
            int n = j >> 8, k = j & 255;
            float v = 0.f;
            if (n < 300)
                v = (k < 128) ? Wl2[k * 300 + n] : Wr2[(k - 128) * 300 + n];
            ushort h, l;
            bsplit(v, h, l);
            g_W2h[j] = h;
            g_W2l[j] = l;
        }
    }
}

// ---------------- CSR build ----------------
__global__ void k_hist(const void* __restrict__ ei, int E) {
    int e = blockIdx.x * blockDim.x + threadIdx.x;
    if (e >= E) return;
    int src, dst;
    load_edge(ei, E, e, src, dst);
    if ((unsigned)dst >= NN) return;
    atomicAdd(&g_degi[dst], 1);
}

__global__ void __launch_bounds__(512) k_scanA() {
    int b = blockIdx.x, t = threadIdx.x;
    int i = b * 512 + t;
    int v = (i < NN) ? g_degi[i] : 0;
#pragma unroll
    for (int o = 16; o; o >>= 1) v += __shfl_xor_sync(0xffffffffu, v, o);
    __shared__ int ws[16];
    if ((t & 31) == 0) ws[t >> 5] = v;
    __syncthreads();
    if (t < 16) {
        int s = ws[t];
#pragma unroll
        for (int o = 8; o; o >>= 1) s += __shfl_xor_sync(0xffffu, s, o);
        if (t == 0) g_part[b] = s;
    }
}

__global__ void __launch_bounds__(128) k_scanB() {
    int t = threadIdx.x;
    int v = (t < SCAN_NB) ? g_part[t] : 0;
    int lane = t & 31, w = t >> 5;
    int x = v;
#pragma unroll
    for (int o = 1; o < 32; o <<= 1) {
        int y = __shfl_up_sync(0xffffffffu, x, o);
        if (lane >= o) x += y;
    }
    __shared__ int wsum[4];
    if (lane == 31) wsum[w] = x;
    __syncthreads();
    int add = 0;
    for (int i = 0; i < w; i++) add += wsum[i];
    int incl = x + add;
    if (t < SCAN_NB) g_partoff[t] = incl - v;
    if (t == SCAN_NB - 1) g_rowptr[NN] = incl;
}

__global__ void __launch_bounds__(512) k_scanC() {
    int b = blockIdx.x, t = threadIdx.x;
    int i = b * 512 + t;
    int v = (i < NN) ? g_degi[i] : 0;
    int lane = t & 31, w = t >> 5;
    int x = v;
#pragma unroll
    for (int o = 1; o < 32; o <<= 1) {
        int y = __shfl_up_sync(0xffffffffu, x, o);
        if (lane >= o) x += y;
    }
    __shared__ int wsum[16];
    __shared__ int woff[16];
    if (lane == 31) wsum[w] = x;
    __syncthreads();
    if (t < 16) {
        int s = wsum[t];
        int xx = s;
#pragma unroll
        for (int o = 1; o < 16; o <<= 1) {
            int y = __shfl_up_sync(0xffffu, xx, o);
            if (t >= o) xx += y;
        }
        woff[t] = xx - s;
    }
    __syncthreads();
    int excl = (x - v) + woff[w] + g_partoff[b];
    if (i < NN) {
        g_rowptr[i] = excl;
        g_cursor[i] = excl;
    }
}

__global__ void k_place(const void* __restrict__ ei, int E) {
    int e = blockIdx.x * blockDim.x + threadIdx.x;
    if (e >= E) return;
    int src, dst;
    load_edge(ei, E, e, src, dst);
    if ((unsigned)src >= NN || (unsigned)dst >= NN) return;
    int pos = atomicAdd(&g_cursor[dst], 1);
    if (pos < EMAX) g_colsrc[pos] = src;
}

// ---------------- gather-aggregate, layer 1 ----------------
__global__ void __launch_bounds__(256) k_gather1() {
    int warp = blockIdx.x * 8 + (threadIdx.x >> 5);
    int lane = threadIdx.x & 31;
    if (warp >= NN) return;
    int n0 = g_rowptr[warp], n1 = g_rowptr[warp + 1];
    float a0 = 0.f, a1 = 0.f;
    for (int jb = n0; jb < n1; jb += 32) {
        int sid = (jb + lane < n1) ? g_colsrc[jb + lane] : 0;
        int m = min(32, n1 - jb);
        for (int k = 0; k < m; k++) {
            int s = __shfl_sync(0xffffffffu, sid, k);
            unsigned vh = *(const unsigned*)(g_A1h + s * 128 + 64 + lane * 2);
            unsigned vl = *(const unsigned*)(g_A1l + s * 128 + 64 + lane * 2);
            a0 += bjoin((ushort)(vh & 0xffff), (ushort)(vl & 0xffff));
            a1 += bjoin((ushort)(vh >> 16), (ushort)(vl >> 16));
        }
    }
    float inv = 1.0f / fmaxf((float)(n1 - n0), 1.0f);
    a0 *= inv; a1 *= inv;
    ushort h0, l0, h1, l1;
    bsplit(a0, h0, l0);
    bsplit(a1, h1, l1);
    *(unsigned*)(g_A1h + warp * 128 + lane * 2) = ((unsigned)h1 << 16) | h0;
    *(unsigned*)(g_A1l + warp * 128 + lane * 2) = ((unsigned)l1 << 16) | l0;
}

// ---------------- gather-aggregate, layer 2 ----------------
__global__ void __launch_bounds__(256) k_gather2() {
    int warp = blockIdx.x * 8 + (threadIdx.x >> 5);
    int lane = threadIdx.x & 31;
    if (warp >= NN) return;
    int n0 = g_rowptr[warp], n1 = g_rowptr[warp + 1];
    float a0 = 0.f, a1 = 0.f, a2 = 0.f, a3 = 0.f;
    for (int jb = n0; jb < n1; jb += 32) {
        int sid = (jb + lane < n1) ? g_colsrc[jb + lane] : 0;
        int m = min(32, n1 - jb);
        for (int k = 0; k < m; k++) {
            int s = __shfl_sync(0xffffffffu, sid, k);
            uint2 vh = *(const uint2*)(g_A2h + (long long)s * 256 + 128 + lane * 4);
            uint2 vl = *(const uint2*)(g_A2l + (long long)s * 256 + 128 + lane * 4);
            a0 += bjoin((ushort)(vh.x & 0xffff), (ushort)(vl.x & 0xffff));
            a1 += bjoin((ushort)(vh.x >> 16), (ushort)(vl.x >> 16));
            a2 += bjoin((ushort)(vh.y & 0xffff), (ushort)(vl.y & 0xffff));
            a3 += bjoin((ushort)(vh.y >> 16), (ushort)(vl.y >> 16));
        }
    }
    float inv = 1.0f / fmaxf((float)(n1 - n0), 1.0f);
    a0 *= inv; a1 *= inv; a2 *= inv; a3 *= inv;
    ushort h0, l0, h1, l1, h2, l2, h3, l3;
    bsplit(a0, h0, l0);
    bsplit(a1, h1, l1);
    bsplit(a2, h2, l2);
    bsplit(a3, h3, l3);
    uint2 oh, ol;
    oh.x = ((unsigned)h1 << 16) | h0;  oh.y = ((unsigned)h3 << 16) | h2;
    ol.x = ((unsigned)l1 << 16) | l0;  ol.y = ((unsigned)l3 << 16) | l2;
    *(uint2*)(g_A2h + (long long)warp * 256 + lane * 4) = oh;
    *(uint2*)(g_A2l + (long long)warp * 256 + lane * 4) = ol;
}

// ---------------- bf16-split tensor-core GEMM mainloop (ldmatrix frags) ----------------
__device__ __forceinline__ void mma_block(const ushort* Ah, const ushort* Al, int astr, int row0,
                                          const ushort* Bh, const ushort* Bl, int bstr, int ncol0,
                                          int nchunks, float acc[2][8][4],
                                          ushort* sAhi, ushort* sAlo,
                                          ushort* sBhi, ushort* sBlo) {
    int tid = threadIdx.x;
    int lane = tid & 31, wid = tid >> 5;
    int warp_m = wid & 3, warp_n = wid >> 2;
    int sub = lane >> 3, li = lane & 7;

    uint32_t uAh = smem_u32(sAhi), uAl = smem_u32(sAlo);
    uint32_t uBh = smem_u32(sBhi), uBl = smem_u32(sBlo);
    // A lane address parts: row = warp_m*32 + mf*16 + li + (sub&1)*8 ; k = kk + (sub>>1)*8
    int a_row_base = warp_m * 32 + li + (sub & 1) * 8;
    int a_k_off = (sub >> 1) * 8;
    // B lane address parts: row = warp_n*64 + nfp*16 + li + (sub>>1)*8 ; k = kk + (sub&1)*8
    int b_row_base = warp_n * 64 + li + (sub >> 1) * 8;
    int b_k_off = (sub & 1) * 8;

    for (int c = 0; c < nchunks; c++) {
        __syncthreads();
        int kb = c * 32;
        copy_tile(Ah, astr, row0, NN, kb, sAhi, tid);
        copy_tile(Al, astr, row0, NN, kb, sAlo, tid);
        copy_tile(Bh, bstr, ncol0, 1 << 30, kb, sBhi, tid);
        copy_tile(Bl, bstr, ncol0, 1 << 30, kb, sBlo, tid);
        __syncthreads();
#pragma unroll
        for (int kk = 0; kk < 32; kk += 16) {
            unsigned ah[2][4], al[2][4];
#pragma unroll
            for (int mf = 0; mf < 2; mf++) {
                uint32_t off = (uint32_t)(((a_row_base + mf * 16) * SSTR + kk + a_k_off) * 2);
                ldsm4(ah[mf], uAh + off);
                ldsm4(al[mf], uAl + off);
            }
#pragma unroll
            for (int nfp = 0; nfp < 4; nfp++) {
                unsigned bh4[4], bl4[4];
                uint32_t off = (uint32_t)(((b_row_base + nfp * 16) * SSTR + kk + b_k_off) * 2);
                ldsm4(bh4, uBh + off);
                ldsm4(bl4, uBl + off);
#pragma unroll
                for (int e = 0; e < 2; e++) {
                    int nf = nfp * 2 + e;
#pragma unroll
                    for (int mf = 0; mf < 2; mf++) {
                        mma16816(acc[mf][nf], ah[mf], bh4 + e * 2);
                        mma16816(acc[mf][nf], ah[mf], bl4 + e * 2);
                        mma16816(acc[mf][nf], al[mf], bh4 + e * 2);
                    }
                }
            }
        }
    }
}

// ---------------- GEMM layer 1: h = drop(relu(A1 @ W1^T + b1)) -> A2h/l[:,128:256] ----------------
__global__ void __launch_bounds__(256) k_mgemm1(const float* __restrict__ b1) {
    __shared__ ushort sAhi[128 * SSTR], sAlo[128 * SSTR];
    __shared__ ushort sBhi[128 * SSTR], sBlo[128 * SSTR];
    float acc[2][8][4];
#pragma unroll
    for (int a = 0; a < 2; a++)
#pragma unroll
        for (int b = 0; b < 8; b++)
#pragma unroll
            for (int j = 0; j < 4; j++) acc[a][b][j] = 0.f;

    int row0 = blockIdx.x * 128;
    mma_block(g_A1h, g_A1l, 128, row0, g_W1h, g_W1l, 128, 0, 4, acc, sAhi, sAlo, sBhi, sBlo);

    int tid = threadIdx.x;
    int lane = tid & 31, wid = tid >> 5;
    int warp_m = wid & 3, warp_n = wid >> 2;
    int g = lane >> 2, t2 = (lane & 3) * 2;
#pragma unroll
    for (int mf = 0; mf < 2; mf++) {
#pragma unroll
        for (int nf = 0; nf < 8; nf++) {
            int col = warp_n * 64 + nf * 8 + t2;
            float2 bv = *(const float2*)(b1 + col);
#pragma unroll
            for (int half = 0; half < 2; half++) {
                int row = row0 + warp_m * 32 + mf * 16 + g + half * 8;
                if (row < NN) {
                    float v0 = acc[mf][nf][half * 2 + 0] + bv.x;
                    float v1 = acc[mf][nf][half * 2 + 1] + bv.y;
                    unsigned base = (unsigned)row * 128u + (unsigned)col;
                    float h0 = tf_drop(fmaxf(v0, 0.f), base + 0u);
                    float h1 = tf_drop(fmaxf(v1, 0.f), base + 1u);
                    ushort hh0, ll0, hh1, ll1;
                    bsplit(h0, hh0, ll0);
                    bsplit(h1, hh1, ll1);
                    long long o = (long long)row * 256 + 128 + col;
                    *(unsigned*)(g_A2h + o) = ((unsigned)hh1 << 16) | hh0;
                    *(unsigned*)(g_A2l + o) = ((unsigned)ll1 << 16) | ll0;
                }
            }
        }
    }
}

// ---------------- GEMM layer 2: out = A2 @ W2^T + b2 ----------------
__global__ void __launch_bounds__(256) k_mgemm2(const float* __restrict__ b2,
                                                float* __restrict__ out) {
    __shared__ ushort sAhi[128 * SSTR], sAlo[128 * SSTR];
    __shared__ ushort sBhi[128 * SSTR], sBlo[128 * SSTR];
    float acc[2][8][4];
#pragma unroll
    for (int a = 0; a < 2; a++)
#pragma unroll
        for (int b = 0; b < 8; b++)
#pragma unroll
            for (int j = 0; j < 4; j++) acc[a][b][j] = 0.f;

    int row0 = blockIdx.x * 128;
    int col0 = blockIdx.y * 128;
    mma_block(g_A2h, g_A2l, 256, row0, g_W2h, g_W2l, 256, col0, 8, acc, sAhi, sAlo, sBhi, sBlo);

    int tid = threadIdx.x;
    int lane = tid & 31, wid = tid >> 5;
    int warp_m = wid & 3, warp_n = wid >> 2;
    int g = lane >> 2, t2 = (lane & 3) * 2;
#pragma unroll
    for (int mf = 0; mf < 2; mf++) {
#pragma unroll
        for (int nf = 0; nf < 8; nf++) {
            int col = col0 + warp_n * 64 + nf * 8 + t2;
            if (col < 300) {
                float2 bv = *(const float2*)(b2 + col);
#pragma unroll
                for (int half = 0; half < 2; half++) {
                    int row = row0 + warp_m * 32 + mf * 16 + g + half * 8;
                    if (row < NN) {
                        float2 o;
                        o.x = acc[mf][nf][half * 2 + 0] + bv.x;
                        o.y = acc[mf][nf][half * 2 + 1] + bv.y;
                        *(float2*)(out + (long long)row * 300 + col) = o;
                    }
                }
            }
        }
    }
}

// ---------------- log_softmax in-place, one warp per row of 300 ----------------
__global__ void __launch_bounds__(256) k_logsoftmax(float* __restrict__ out) {
    int gid = blockIdx.x * 256 + threadIdx.x;
    int row = gid >> 5;
    int lane = gid & 31;
    if (row >= NN) return;
    float* p = out + (long long)row * 300;
    float vals[10];
    float m = -3.4e38f;
#pragma unroll
    for (int i = 0; i < 10; i++) {
        int c = lane + i * 32;
        vals[i] = (c < 300) ? p[c] : -3.4e38f;
        m = fmaxf(m, vals[i]);
    }
#pragma unroll
    for (int o = 16; o; o >>= 1) m = fmaxf(m, __shfl_xor_sync(0xffffffffu, m, o));
    float s = 0.f;
#pragma unroll
    for (int i = 0; i < 10; i++) {
        int c = lane + i * 32;
        if (c < 300) s += __expf(vals[i] - m);
    }
#pragma unroll
    for (int o = 16; o; o >>= 1) s += __shfl_xor_sync(0xffffffffu, s, o);
    float lse = m + __logf(s);
#pragma unroll
    for (int i = 0; i < 10; i++) {
        int c = lane + i * 32;
        if (c < 300) p[c] = vals[i] - lse;
    }
}

// ---------------- launch ----------------
extern "C" void kernel_launch(void* const* d_in, const int* in_sizes, int n_in,
                              void* d_out, int out_size) {
    const float* x        = (const float*)d_in[0];
    const void*  ei       = (const void*)d_in[1];
    const float* Wl1      = (const float*)d_in[2];
    const float* Wr1      = (const float*)d_in[3];
    const float* b1       = (const float*)d_in[4];
    const float* Wl2      = (const float*)d_in[5];
    const float* Wr2      = (const float*)d_in[6];
    const float* b2       = (const float*)d_in[7];
    float* out            = (float*)d_out;
    int E = in_sizes[1] / 2;

    k_detect<<<1, 256>>>(ei);
    k_init<<<4096, 256>>>(x, Wl1, Wr1, Wl2, Wr2);
    k_hist<<<(E + 255) / 256, 256>>>(ei, E);
    k_scanA<<<SCAN_NB, 512>>>();
    k_scanB<<<1, 128>>>();
    k_scanC<<<SCAN_NB, 512>>>();
    k_place<<<(E + 255) / 256, 256>>>(ei, E);
    k_gather1<<<(NN + 7) / 8, 256>>>();
    k_mgemm1<<<(NN + 127) / 128, 256>>>(b1);
    k_gather2<<<(NN + 7) / 8, 256>>>();
    dim3 g2((NN + 127) / 128, 3);
    k_mgemm2<<<g2, 256>>>(b2, out);
    k_logsoftmax<<<(NN * 32 + 255) / 256, 256>>>(out);
}

// round 17
// speedup vs baseline: 1.1904x; 1.1904x over previous
#include <cuda_runtime.h>
#include <cuda_bf16.h>
#include <cstdint>

#define NN 50000
#define EMAX 1000000
#define SCAN_NB ((NN + 511) / 512)   // 98 chunks of 512

// ---------------- scratch: hi/lo bf16 number system (no allocations) ----------------
static __device__ __align__(16) ushort g_A1h[NN * 128];  // [agg(x) | x] hi
static __device__ __align__(16) ushort g_A1l[NN * 128];  // lo
static __device__ __align__(16) ushort g_A2h[NN * 256];  // [agg(h) | h] hi
static __device__ __align__(16) ushort g_A2l[NN * 256];  // lo
static __device__ __align__(16) ushort g_W1h[128 * 128]; // [Wl1;Wr1]^T hi
static __device__ __align__(16) ushort g_W1l[128 * 128];
static __device__ __align__(16) ushort g_W2h[384 * 256]; // [Wl2;Wr2]^T hi, n-padded
static __device__ __align__(16) ushort g_W2l[384 * 256];
static __device__ int g_idx64;
static __device__ int g_degi[NN];
static __device__ int g_rowptr[NN + 1];
static __device__ int g_cursor[NN];
static __device__ int g_colsrc[EMAX];
static __device__ int g_part[128];
static __device__ int g_partoff[128];

__device__ __forceinline__ void bsplit(float v, ushort& h, ushort& l) {
    __nv_bfloat16 hb = __float2bfloat16(v);
    h = __bfloat16_as_ushort(hb);
    l = __bfloat16_as_ushort(__float2bfloat16(v - __bfloat162float(hb)));
}
__device__ __forceinline__ float bjoin(ushort h, ushort l) {
    return __bfloat162float(__ushort_as_bfloat16(h)) +
           __bfloat162float(__ushort_as_bfloat16(l));
}

// ---------------- threefry2x32 dropout, JAX partitionable (o0 ^ o1) ----------------
__device__ __forceinline__ float tf_drop(float v, unsigned idx) {
    unsigned x0 = 0u, x1 = idx;
    const unsigned k0 = 0u, k1 = 42u;
    const unsigned k2c = 0u ^ 42u ^ 0x1BD11BDAu;
    x0 += k0; x1 += k1;
#define TF_R(r) { x0 += x1; x1 = __funnelshift_l(x1, x1, (r)); x1 ^= x0; }
    TF_R(13) TF_R(15) TF_R(26) TF_R(6)
    x0 += k1;  x1 += k2c + 1u;
    TF_R(17) TF_R(29) TF_R(16) TF_R(24)
    x0 += k2c; x1 += k0 + 2u;
    TF_R(13) TF_R(15) TF_R(26) TF_R(6)
    x0 += k0;  x1 += k1 + 3u;
    TF_R(17) TF_R(29) TF_R(16) TF_R(24)
    x0 += k1;  x1 += k2c + 4u;
    TF_R(13) TF_R(15) TF_R(26) TF_R(6)
    x0 += k2c; x1 += k0 + 5u;
#undef TF_R
    unsigned bits = x0 ^ x1;
    float u = __uint_as_float((bits >> 9) | 0x3f800000u) - 1.0f;
    return (u < 0.5f) ? v * 2.0f : 0.0f;
}

// ---------------- mma.sync m16n8k16 bf16 ----------------
__device__ __forceinline__ void mma16816(float* c, const unsigned* a, const unsigned* b) {
    asm volatile(
        "mma.sync.aligned.m16n8k16.row.col.f32.bf16.bf16.f32 "
        "{%0,%1,%2,%3}, {%4,%5,%6,%7}, {%8,%9}, {%0,%1,%2,%3};"
        : "+f"(c[0]), "+f"(c[1]), "+f"(c[2]), "+f"(c[3])
        : "r"(a[0]), "r"(a[1]), "r"(a[2]), "r"(a[3]), "r"(b[0]), "r"(b[1]));
}

__device__ __forceinline__ uint32_t smem_u32(const void* p) {
    uint32_t a;
    asm("{ .reg .u64 t; cvta.to.shared.u64 t, %1; cvt.u32.u64 %0, t; }" : "=r"(a) : "l"(p));
    return a;
}

#define CP_COMMIT() asm volatile("cp.async.commit_group;" ::: "memory")
#define CP_WAIT(n)  asm volatile("cp.async.wait_group %0;" :: "n"(n) : "memory")

#define SSTR 40        // smem row stride (ushorts): 32 data + 8 pad
#define TILE_US (128 * SSTR)     // 5120 ushorts per tile
#define BUF_US  (4 * TILE_US)    // 20480 ushorts per buffer (Ah,Al,Bh,Bl)
#define SMEM_BYTES (2 * BUF_US * 2)  // 81920 bytes

// async copy of a 128x32 ushort tile into smem (zero-fill for OOB rows)
__device__ __forceinline__ void copy_tile_async(const ushort* __restrict__ src, int stride,
                                                int r0, int rowlim, int kb,
                                                ushort* dst, int tid) {
    for (int i = tid; i < 512; i += 256) {
        int r = i >> 2, c8 = (i & 3) * 8;
        int gr = r0 + r;
        int valid = (gr < rowlim) ? 16 : 0;
        int gsafe = (gr < rowlim) ? gr : 0;
        const ushort* s = src + (long long)gsafe * stride + kb + c8;
        uint32_t d = smem_u32(dst + r * SSTR + c8);
        asm volatile("cp.async.cg.shared.global [%0], [%1], 16, %2;"
                     :: "r"(d), "l"(s), "r"(valid) : "memory");
    }
}

// ---------------- dtype detection ----------------
__global__ void k_detect(const void* __restrict__ ei) {
    const long long* p = (const long long*)ei;
    long long v = p[threadIdx.x];
    unsigned bad = __ballot_sync(0xffffffffu, (unsigned long long)v >= (unsigned long long)NN);
    __shared__ int s_bad;
    if (threadIdx.x == 0) s_bad = 0;
    __syncthreads();
    if ((threadIdx.x & 31) == 0 && bad) atomicOr(&s_bad, 1);
    __syncthreads();
    if (threadIdx.x == 0) g_idx64 = s_bad ? 0 : 1;
}

__device__ __forceinline__ void load_edge(const void* ei, int E, int e, int& src, int& dst) {
    if (g_idx64) {
        const long long* p = (const long long*)ei;
        src = (int)p[e];
        dst = (int)p[E + e];
    } else {
        const int* p = (const int*)ei;
        src = p[e];
        dst = p[E + e];
    }
}

// ---------------- init: split x + weights into hi/lo, zero deg ----------------
__global__ void k_init(const float* __restrict__ x,
                       const float* __restrict__ Wl1, const float* __restrict__ Wr1,
                       const float* __restrict__ Wl2, const float* __restrict__ Wr2) {
    const int T0 = NN * 64;
    const int T1 = T0 + NN;
    const int T2 = T1 + 128 * 128;
    const int T3 = T2 + 384 * 256;
    for (int i = blockIdx.x * blockDim.x + threadIdx.x; i < T3;
         i += gridDim.x * blockDim.x) {
        if (i < T0) {
            int row = i >> 6, col = i & 63;
            ushort h, l;
            bsplit(x[i], h, l);
            g_A1h[row * 128 + 64 + col] = h;
            g_A1l[row * 128 + 64 + col] = l;
        } else if (i < T1) {
            g_degi[i - T0] = 0;
        } else if (i < T2) {
            int j = i - T1;
            int n = j >> 7, k = j & 127;
            float v = (k < 64) ? Wl1[k * 128 + n] : Wr1[(k - 64) * 128 + n];
            ushort h, l;
            bsplit(v, h, l);
            g_W1h[j] = h;
            g_W1l[j] = l;
        } else {
            int j = i - T2;
            int n = j >> 8, k = j & 255;
            float v = 0.f;
            if (n < 300)
                v = (k < 128) ? Wl2[k * 300 + n] : Wr2[(k - 128) * 300 + n];
            ushort h, l;
            bsplit(v, h, l);
            g_W2h[j] = h;
            g_W2l[j] = l;
        }
    }
}

// ---------------- CSR build ----------------
__global__ void k_hist(const void* __restrict__ ei, int E) {
    int e = blockIdx.x * blockDim.x + threadIdx.x;
    if (e >= E) return;
    int src, dst;
    load_edge(ei, E, e, src, dst);
    if ((unsigned)dst >= NN) return;
    atomicAdd(&g_degi[dst], 1);
}

__global__ void __launch_bounds__(512) k_scanA() {
    int b = blockIdx.x, t = threadIdx.x;
    int i = b * 512 + t;
    int v = (i < NN) ? g_degi[i] : 0;
#pragma unroll
    for (int o = 16; o; o >>= 1) v += __shfl_xor_sync(0xffffffffu, v, o);
    __shared__ int ws[16];
    if ((t & 31) == 0) ws[t >> 5] = v;
    __syncthreads();
    if (t < 16) {
        int s = ws[t];
#pragma unroll
        for (int o = 8; o; o >>= 1) s += __shfl_xor_sync(0xffffu, s, o);
        if (t == 0) g_part[b] = s;
    }
}

__global__ void __launch_bounds__(128) k_scanB() {
    int t = threadIdx.x;
    int v = (t < SCAN_NB) ? g_part[t] : 0;
    int lane = t & 31, w = t >> 5;
    int x = v;
#pragma unroll
    for (int o = 1; o < 32; o <<= 1) {
        int y = __shfl_up_sync(0xffffffffu, x, o);
        if (lane >= o) x += y;
    }
    __shared__ int wsum[4];
    if (lane == 31) wsum[w] = x;
    __syncthreads();
    int add = 0;
    for (int i = 0; i < w; i++) add += wsum[i];
    int incl = x + add;
    if (t < SCAN_NB) g_partoff[t] = incl - v;
    if (t == SCAN_NB - 1) g_rowptr[NN] = incl;
}

__global__ void __launch_bounds__(512) k_scanC() {
    int b = blockIdx.x, t = threadIdx.x;
    int i = b * 512 + t;
    int v = (i < NN) ? g_degi[i] : 0;
    int lane = t & 31, w = t >> 5;
    int x = v;
#pragma unroll
    for (int o = 1; o < 32; o <<= 1) {
        int y = __shfl_up_sync(0xffffffffu, x, o);
        if (lane >= o) x += y;
    }
    __shared__ int wsum[16];
    __shared__ int woff[16];
    if (lane == 31) wsum[w] = x;
    __syncthreads();
    if (t < 16) {
        int s = wsum[t];
        int xx = s;
#pragma unroll
        for (int o = 1; o < 16; o <<= 1) {
            int y = __shfl_up_sync(0xffffu, xx, o);
            if (t >= o) xx += y;
        }
        woff[t] = xx - s;
    }
    __syncthreads();
    int excl = (x - v) + woff[w] + g_partoff[b];
    if (i < NN) {
        g_rowptr[i] = excl;
        g_cursor[i] = excl;
    }
}

__global__ void k_place(const void* __restrict__ ei, int E) {
    int e = blockIdx.x * blockDim.x + threadIdx.x;
    if (e >= E) return;
    int src, dst;
    load_edge(ei, E, e, src, dst);
    if ((unsigned)src >= NN || (unsigned)dst >= NN) return;
    int pos = atomicAdd(&g_cursor[dst], 1);
    if (pos < EMAX) g_colsrc[pos] = src;
}

// ---------------- gather-aggregate, layer 1 ----------------
__global__ void __launch_bounds__(256) k_gather1() {
    int warp = blockIdx.x * 8 + (threadIdx.x >> 5);
    int lane = threadIdx.x & 31;
    if (warp >= NN) return;
    int n0 = g_rowptr[warp], n1 = g_rowptr[warp + 1];
    float a0 = 0.f, a1 = 0.f;
    for (int jb = n0; jb < n1; jb += 32) {
        int sid = (jb + lane < n1) ? g_colsrc[jb + lane] : 0;
        int m = min(32, n1 - jb);
        for (int k = 0; k < m; k++) {
            int s = __shfl_sync(0xffffffffu, sid, k);
            unsigned vh = *(const unsigned*)(g_A1h + s * 128 + 64 + lane * 2);
            unsigned vl = *(const unsigned*)(g_A1l + s * 128 + 64 + lane * 2);
            a0 += bjoin((ushort)(vh & 0xffff), (ushort)(vl & 0xffff));
            a1 += bjoin((ushort)(vh >> 16), (ushort)(vl >> 16));
        }
    }
    float inv = 1.0f / fmaxf((float)(n1 - n0), 1.0f);
    a0 *= inv; a1 *= inv;
    ushort h0, l0, h1, l1;
    bsplit(a0, h0, l0);
    bsplit(a1, h1, l1);
    *(unsigned*)(g_A1h + warp * 128 + lane * 2) = ((unsigned)h1 << 16) | h0;
    *(unsigned*)(g_A1l + warp * 128 + lane * 2) = ((unsigned)l1 << 16) | l0;
}

// ---------------- gather-aggregate, layer 2 ----------------
__global__ void __launch_bounds__(256) k_gather2() {
    int warp = blockIdx.x * 8 + (threadIdx.x >> 5);
    int lane = threadIdx.x & 31;
    if (warp >= NN) return;
    int n0 = g_rowptr[warp], n1 = g_rowptr[warp + 1];
    float a0 = 0.f, a1 = 0.f, a2 = 0.f, a3 = 0.f;
    for (int jb = n0; jb < n1; jb += 32) {
        int sid = (jb + lane < n1) ? g_colsrc[jb + lane] : 0;
        int m = min(32, n1 - jb);
        for (int k = 0; k < m; k++) {
            int s = __shfl_sync(0xffffffffu, sid, k);
            uint2 vh = *(const uint2*)(g_A2h + (long long)s * 256 + 128 + lane * 4);
            uint2 vl = *(const uint2*)(g_A2l + (long long)s * 256 + 128 + lane * 4);
            a0 += bjoin((ushort)(vh.x & 0xffff), (ushort)(vl.x & 0xffff));
            a1 += bjoin((ushort)(vh.x >> 16), (ushort)(vl.x >> 16));
            a2 += bjoin((ushort)(vh.y & 0xffff), (ushort)(vl.y & 0xffff));
            a3 += bjoin((ushort)(vh.y >> 16), (ushort)(vl.y >> 16));
        }
    }
    float inv = 1.0f / fmaxf((float)(n1 - n0), 1.0f);
    a0 *= inv; a1 *= inv; a2 *= inv; a3 *= inv;
    ushort h0, l0, h1, l1, h2, l2, h3, l3;
    bsplit(a0, h0, l0);
    bsplit(a1, h1, l1);
    bsplit(a2, h2, l2);
    bsplit(a3, h3, l3);
    uint2 oh, ol;
    oh.x = ((unsigned)h1 << 16) | h0;  oh.y = ((unsigned)h3 << 16) | h2;
    ol.x = ((unsigned)l1 << 16) | l0;  ol.y = ((unsigned)l3 << 16) | l2;
    *(uint2*)(g_A2h + (long long)warp * 256 + lane * 4) = oh;
    *(uint2*)(g_A2l + (long long)warp * 256 + lane * 4) = ol;
}

// ---------------- bf16-split tensor-core GEMM mainloop (double-buffered cp.async) ----------------
// Tiles per buffer: [Ah, Al, Bh, Bl], each 128xSSTR ushorts.
__device__ __forceinline__ void issue_chunk(const ushort* Ah, const ushort* Al, int astr, int row0,
                                            const ushort* Bh, const ushort* Bl, int bstr, int ncol0,
                                            int kb, ushort* buf, int tid) {
    copy_tile_async(Ah, astr, row0, NN, kb, buf + 0 * TILE_US, tid);
    copy_tile_async(Al, astr, row0, NN, kb, buf + 1 * TILE_US, tid);
    copy_tile_async(Bh, bstr, ncol0, 1 << 30, kb, buf + 2 * TILE_US, tid);
    copy_tile_async(Bl, bstr, ncol0, 1 << 30, kb, buf + 3 * TILE_US, tid);
    CP_COMMIT();
}

__device__ __forceinline__ void mma_block(const ushort* Ah, const ushort* Al, int astr, int row0,
                                          const ushort* Bh, const ushort* Bl, int bstr, int ncol0,
                                          int nchunks, float acc[2][8][4], ushort* S) {
    int tid = threadIdx.x;
    int lane = tid & 31, wid = tid >> 5;
    int warp_m = wid & 3, warp_n = wid >> 2;
    int g = lane >> 2, t2 = (lane & 3) * 2;

    issue_chunk(Ah, Al, astr, row0, Bh, Bl, bstr, ncol0, 0, S, tid);

    for (int c = 0; c < nchunks; c++) {
        if (c + 1 < nchunks) {
            issue_chunk(Ah, Al, astr, row0, Bh, Bl, bstr, ncol0,
                        (c + 1) * 32, S + ((c + 1) & 1) * BUF_US, tid);
            CP_WAIT(1);
        } else {
            CP_WAIT(0);
        }
        __syncthreads();
        ushort* cur = S + (c & 1) * BUF_US;
        ushort* sAhi = cur + 0 * TILE_US;
        ushort* sAlo = cur + 1 * TILE_US;
        ushort* sBhi = cur + 2 * TILE_US;
        ushort* sBlo = cur + 3 * TILE_US;
#pragma unroll
        for (int kk = 0; kk < 32; kk += 16) {
            unsigned ah[2][4], al[2][4];
#pragma unroll
            for (int mf = 0; mf < 2; mf++) {
                int m = warp_m * 32 + mf * 16 + g;
                int k0 = kk + t2;
                ah[mf][0] = *(const unsigned*)(sAhi + m * SSTR + k0);
                ah[mf][1] = *(const unsigned*)(sAhi + (m + 8) * SSTR + k0);
                ah[mf][2] = *(const unsigned*)(sAhi + m * SSTR + k0 + 8);
                ah[mf][3] = *(const unsigned*)(sAhi + (m + 8) * SSTR + k0 + 8);
                al[mf][0] = *(const unsigned*)(sAlo + m * SSTR + k0);
                al[mf][1] = *(const unsigned*)(sAlo + (m + 8) * SSTR + k0);
                al[mf][2] = *(const unsigned*)(sAlo + m * SSTR + k0 + 8);
                al[mf][3] = *(const unsigned*)(sAlo + (m + 8) * SSTR + k0 + 8);
            }
#pragma unroll
            for (int nf = 0; nf < 8; nf++) {
                int n = warp_n * 64 + nf * 8 + g;
                int k0 = kk + t2;
                unsigned bh[2], bl[2];
                bh[0] = *(const unsigned*)(sBhi + n * SSTR + k0);
                bh[1] = *(const unsigned*)(sBhi + n * SSTR + k0 + 8);
                bl[0] = *(const unsigned*)(sBlo + n * SSTR + k0);
                bl[1] = *(const unsigned*)(sBlo + n * SSTR + k0 + 8);
#pragma unroll
                for (int mf = 0; mf < 2; mf++) {
                    mma16816(acc[mf][nf], ah[mf], bh);
                    mma16816(acc[mf][nf], ah[mf], bl);
                    mma16816(acc[mf][nf], al[mf], bh);
                }
            }
        }
        __syncthreads();
    }
}

// ---------------- GEMM layer 1: h = drop(relu(A1 @ W1^T + b1)) -> A2h/l[:,128:256] ----------------
__global__ void __launch_bounds__(256) k_mgemm1(const float* __restrict__ b1) {
    extern __shared__ ushort S[];
    float acc[2][8][4];
#pragma unroll
    for (int a = 0; a < 2; a++)
#pragma unroll
        for (int b = 0; b < 8; b++)
#pragma unroll
            for (int j = 0; j < 4; j++) acc[a][b][j] = 0.f;

    int row0 = blockIdx.x * 128;
    mma_block(g_A1h, g_A1l, 128, row0, g_W1h, g_W1l, 128, 0, 4, acc, S);

    int tid = threadIdx.x;
    int lane = tid & 31, wid = tid >> 5;
    int warp_m = wid & 3, warp_n = wid >> 2;
    int g = lane >> 2, t2 = (lane & 3) * 2;
#pragma unroll
    for (int mf = 0; mf < 2; mf++) {
#pragma unroll
        for (int nf = 0; nf < 8; nf++) {
            int col = warp_n * 64 + nf * 8 + t2;
            float2 bv = *(const float2*)(b1 + col);
#pragma unroll
            for (int half = 0; half < 2; half++) {
                int row = row0 + warp_m * 32 + mf * 16 + g + half * 8;
                if (row < NN) {
                    float v0 = acc[mf][nf][half * 2 + 0] + bv.x;
                    float v1 = acc[mf][nf][half * 2 + 1] + bv.y;
                    unsigned base = (unsigned)row * 128u + (unsigned)col;
                    float h0 = tf_drop(fmaxf(v0, 0.f), base + 0u);
                    float h1 = tf_drop(fmaxf(v1, 0.f), base + 1u);
                    ushort hh0, ll0, hh1, ll1;
                    bsplit(h0, hh0, ll0);
                    bsplit(h1, hh1, ll1);
                    long long o = (long long)row * 256 + 128 + col;
                    *(unsigned*)(g_A2h + o) = ((unsigned)hh1 << 16) | hh0;
                    *(unsigned*)(g_A2l + o) = ((unsigned)ll1 << 16) | ll0;
                }
            }
        }
    }
}

// ---------------- GEMM layer 2: out = A2 @ W2^T + b2 ----------------
__global__ void __launch_bounds__(256) k_mgemm2(const float* __restrict__ b2,
                                                float* __restrict__ out) {
    extern __shared__ ushort S[];
    float acc[2][8][4];
#pragma unroll
    for (int a = 0; a < 2; a++)
#pragma unroll
        for (int b = 0; b < 8; b++)
#pragma unroll
            for (int j = 0; j < 4; j++) acc[a][b][j] = 0.f;

    int row0 = blockIdx.x * 128;
    int col0 = blockIdx.y * 128;
    mma_block(g_A2h, g_A2l, 256, row0, g_W2h, g_W2l, 256, col0, 8, acc, S);

    int tid = threadIdx.x;
    int lane = tid & 31, wid = tid >> 5;
    int warp_m = wid & 3, warp_n = wid >> 2;
    int g = lane >> 2, t2 = (lane & 3) * 2;
#pragma unroll
    for (int mf = 0; mf < 2; mf++) {
#pragma unroll
        for (int nf = 0; nf < 8; nf++) {
            int col = col0 + warp_n * 64 + nf * 8 + t2;
            if (col < 300) {
                float2 bv = *(const float2*)(b2 + col);
#pragma unroll
                for (int half = 0; half < 2; half++) {
                    int row = row0 + warp_m * 32 + mf * 16 + g + half * 8;
                    if (row < NN) {
                        float2 o;
                        o.x = acc[mf][nf][half * 2 + 0] + bv.x;
                        o.y = acc[mf][nf][half * 2 + 1] + bv.y;
                        *(float2*)(out + (long long)row * 300 + col) = o;
                    }
                }
            }
        }
    }
}

// ---------------- log_softmax in-place, one warp per row of 300 ----------------
__global__ void __launch_bounds__(256) k_logsoftmax(float* __restrict__ out) {
    int gid = blockIdx.x * 256 + threadIdx.x;
    int row = gid >> 5;
    int lane = gid & 31;
    if (row >= NN) return;
    float* p = out + (long long)row * 300;
    float vals[10];
    float m = -3.4e38f;
#pragma unroll
    for (int i = 0; i < 10; i++) {
        int c = lane + i * 32;
        vals[i] = (c < 300) ? p[c] : -3.4e38f;
        m = fmaxf(m, vals[i]);
    }
#pragma unroll
    for (int o = 16; o; o >>= 1) m = fmaxf(m, __shfl_xor_sync(0xffffffffu, m, o));
    float s = 0.f;
#pragma unroll
    for (int i = 0; i < 10; i++) {
        int c = lane + i * 32;
        if (c < 300) s += __expf(vals[i] - m);
    }
#pragma unroll
    for (int o = 16; o; o >>= 1) s += __shfl_xor_sync(0xffffffffu, s, o);
    float lse = m + __logf(s);
#pragma unroll
    for (int i = 0; i < 10; i++) {
        int c = lane + i * 32;
        if (c < 300) p[c] = vals[i] - lse;
    }
}

// ---------------- launch ----------------
extern "C" void kernel_launch(void* const* d_in, const int* in_sizes, int n_in,
                              void* d_out, int out_size) {
    const float* x        = (const float*)d_in[0];
    const void*  ei       = (const void*)d_in[1];
    const float* Wl1      = (const float*)d_in[2];
    const float* Wr1      = (const float*)d_in[3];
    const float* b1       = (const float*)d_in[4];
    const float* Wl2      = (const float*)d_in[5];
    const float* Wr2      = (const float*)d_in[6];
    const float* b2       = (const float*)d_in[7];
    float* out            = (float*)d_out;
    int E = in_sizes[1] / 2;

    cudaFuncSetAttribute(k_mgemm1, cudaFuncAttributeMaxDynamicSharedMemorySize, SMEM_BYTES);
    cudaFuncSetAttribute(k_mgemm2, cudaFuncAttributeMaxDynamicSharedMemorySize, SMEM_BYTES);

    k_detect<<<1, 256>>>(ei);
    k_init<<<4096, 256>>>(x, Wl1, Wr1, Wl2, Wr2);
    k_hist<<<(E + 255) / 256, 256>>>(ei, E);
    k_scanA<<<SCAN_NB, 512>>>();
    k_scanB<<<1, 128>>>();
    k_scanC<<<SCAN_NB, 512>>>();
    k_place<<<(E + 255) / 256, 256>>>(ei, E);
    k_gather1<<<(NN + 7) / 8, 256>>>();
    k_mgemm1<<<(NN + 127) / 128, 256, SMEM_BYTES>>>(b1);
    k_gather2<<<(NN + 7) / 8, 256>>>();
    dim3 g2((NN + 127) / 128, 3);
    k_mgemm2<<<g2, 256, SMEM_BYTES>>>(b2, out);
    k_logsoftmax<<<(NN * 32 + 255) / 256, 256>>>(out);
}